// round 11
// baseline (speedup 1.0000x reference)
#include <cuda_runtime.h>
#include <cuda_bf16.h>
#include <cstdint>

#define N_NODES     500000
#define N_INC       2000000
#define N_HEDGES    100000
#define N_GRAPHS    512
#define CH          64
#define FULLM       0xffffffffu
#define N_TILES     31250          // N_NODES / 16 (even)
#define WSTRIDE     68             // padded smem row stride for A/W tiles
#define CSTRIDE     36             // C-stage stride: bank=(4r+c)%32 conflict-free
#define NB_SCANN    489            // ceil(N_NODES/1024)
#define NB_SCANE    98             // ceil(N_HEDGES/1024)
#define NB_SCANT    (NB_SCANN + NB_SCANE)   // 587

// ---------------- scratch (device globals; no allocation allowed) ----------------
__device__ __align__(256) uint32_t g_xt_h[(long)N_NODES * 32];   // 64 MB bf16 rows (128B each)
__device__ __align__(256) uint32_t g_m_h [(long)N_HEDGES * 32];  // 12.8 MB bf16 rows
__device__ int   g_degN[N_NODES];
__device__ int   g_degE[N_HEDGES];
__device__ int   g_rowptr[N_NODES];         // after fill: rowptr[v] = END of node v's segment
__device__ int   g_colptr[N_HEDGES];        // after fill: colptr[e] = END of edge e's segment
__device__ int   g_csr[N_INC];              // edge ids, grouped by node
__device__ int   g_csrE[N_INC];             // node ids, grouped by edge
__device__ int   g_agg [NB_SCANT];          // decoupled-lookback aggregates
__device__ int   g_pref[NB_SCANT];          // inclusive prefixes
__device__ int   g_stat[NB_SCANT];          // 0 invalid / 1 agg / 2 prefix
__device__ float g_gsum[N_GRAPHS];
__device__ int   g_gcnt[N_GRAPHS];

// ---------------- small helpers ----------------
__device__ __forceinline__ uint32_t f2_to_bf(float a, float b) {
    uint32_t r;
    asm("cvt.rn.bf16x2.f32 %0, %1, %2;" : "=r"(r) : "f"(b), "f"(a));
    return r;
}
__device__ __forceinline__ float2 bf_to_f2(uint32_t p) {
    return __bfloat1622float2(*reinterpret_cast<const __nv_bfloat162*>(&p));
}
__device__ __forceinline__ uint32_t tf32r(float f) {
    uint32_t r;
    asm("cvt.rna.tf32.f32 %0, %1;" : "=r"(r) : "f"(f));
    return r;
}
__device__ __forceinline__ void mma_tf32(float c[4],
                                         uint32_t a0, uint32_t a1, uint32_t a2, uint32_t a3,
                                         uint32_t b0, uint32_t b1) {
    asm volatile("mma.sync.aligned.m16n8k8.row.col.f32.tf32.tf32.f32 "
                 "{%0,%1,%2,%3}, {%4,%5,%6,%7}, {%8,%9}, {%0,%1,%2,%3};"
                 : "+f"(c[0]), "+f"(c[1]), "+f"(c[2]), "+f"(c[3])
                 : "r"(a0), "r"(a1), "r"(a2), "r"(a3), "r"(b0), "r"(b1));
}

// ---------------- zero scratch ----------------
__global__ void k_zero() {
    int t = blockIdx.x * blockDim.x + threadIdx.x;
    int S = gridDim.x * blockDim.x;
    for (int j = t; j < N_NODES; j += S) g_degN[j] = 0;
    for (int j = t; j < N_HEDGES; j += S) g_degE[j] = 0;
    for (int j = t; j < N_GRAPHS; j += S) { g_gsum[j] = 0.f; g_gcnt[j] = 0; }
    for (int j = t; j < NB_SCANT; j += S) g_stat[j] = 0;
}

// ---------------- degree histograms + graph-size histogram ----------------
__global__ void k_hist(const int* __restrict__ row, const int* __restrict__ col,
                       const int* __restrict__ batch) {
    int i = blockIdx.x * blockDim.x + threadIdx.x;
    if (i < N_INC) {
        atomicAdd(&g_degN[row[i]], 1);
        atomicAdd(&g_degE[col[i]], 1);
    }
    unsigned act = __ballot_sync(FULLM, i < N_NODES);
    if (i < N_NODES) {
        int g = batch[i];
        unsigned mask = __match_any_sync(act, g);
        int leader = __ffs(mask) - 1;
        if ((threadIdx.x & 31) == leader) atomicAdd(&g_gcnt[g], __popc(mask));
    }
}

// ---------------- single-kernel exclusive scans via decoupled lookback ----------------
// Two independent chains: node blocks [0, NB_SCANN), edge blocks [NB_SCANN, NB_SCANT).
// Chain-first block publishes stat=2 directly, so lookback never crosses chains.
__global__ void k_scan() {
    int mode = blockIdx.x >= NB_SCANN;
    int blk = mode ? blockIdx.x - NB_SCANN : blockIdx.x;
    const int* __restrict__ in = mode ? g_degE : g_degN;
    int* __restrict__ out = mode ? g_colptr : g_rowptr;
    int n = mode ? N_HEDGES : N_NODES;
    int gix = blockIdx.x;

    __shared__ int sh[1024];
    __shared__ int s_off;
    int tid = threadIdx.x;
    int i = blk * 1024 + tid;
    int v = (i < n) ? in[i] : 0;
    sh[tid] = v;
    __syncthreads();
#pragma unroll
    for (int off = 1; off < 1024; off <<= 1) {
        int t = (tid >= off) ? sh[tid - off] : 0;
        __syncthreads();
        sh[tid] += t;
        __syncthreads();
    }

    if (tid == 1023) {
        int total = sh[1023];
        if (blk == 0) {
            g_pref[gix] = total;
            __threadfence();
            g_stat[gix] = 2;
            s_off = 0;
        } else {
            g_agg[gix] = total;
            __threadfence();
            g_stat[gix] = 1;
            int sum = 0;
            int p = gix - 1;
            while (true) {
                int st;
                do { st = ((volatile int*)g_stat)[p]; } while (st == 0);
                __threadfence();
                if (st == 1) { sum += ((volatile int*)g_agg)[p]; p--; }
                else         { sum += ((volatile int*)g_pref)[p]; break; }
            }
            g_pref[gix] = sum + total;
            __threadfence();
            g_stat[gix] = 2;
            s_off = sum;
        }
    }
    __syncthreads();
    if (i < n) out[i] = s_off + sh[tid] - v;   // exclusive prefix
}

// ---------------- fill both CSRs (atomicAdd directly on the ptr arrays) ----------------
// After this kernel ptr[v] = END of v's segment; beg(v) = v ? ptr[v-1] : 0.
__global__ void k_fill(const int* __restrict__ row, const int* __restrict__ col) {
    int i = blockIdx.x * blockDim.x + threadIdx.x;
    if (i < N_INC) {
        int r = row[i], c = col[i];
        int pr = atomicAdd(&g_rowptr[r], 1);
        g_csr[pr] = c;
        int pc = atomicAdd(&g_colptr[c], 1);
        g_csrE[pc] = r;
    }
}

// ---------------- k_xt: xt = x W1 + b1 via tf32 mma ----------------
extern __shared__ uint32_t xt_smem[];
__global__ void __launch_bounds__(128) k_xt(const float* __restrict__ x,
                                            const float* __restrict__ W,
                                            const float* __restrict__ b) {
    uint32_t* Ws = xt_smem;                       // tf32 bits, [n][k] stride 68
    __shared__ float bs[CH];
    for (int i = threadIdx.x; i < CH * CH; i += 128) {
        int k = i >> 6, n = i & 63;
        Ws[n * WSTRIDE + k] = tf32r(W[i]);
    }
    if (threadIdx.x < CH) bs[threadIdx.x] = b[threadIdx.x];
    __syncthreads();

    int lane = threadIdx.x & 31;
    int wid = threadIdx.x >> 5;
    int wg = blockIdx.x * 4 + wid;
    int tileBase = wg * 2;
    if (tileBase >= N_TILES) return;   // N_TILES even -> both tiles valid
    int row0 = tileBase * 16;
    uint32_t* myA = xt_smem + CH * WSTRIDE + wid * (32 * WSTRIDE);

    const float* xbase = x + (long)row0 * CH;
#pragma unroll
    for (int i = 0; i < 16; i++) {
        int idx = i * 32 + lane;
        int r = idx >> 4, c4 = (idx & 15) * 4;
        float4 v = *(const float4*)(xbase + r * CH + c4);
        *(uint4*)&myA[r * WSTRIDE + c4] =
            make_uint4(tf32r(v.x), tf32r(v.y), tf32r(v.z), tf32r(v.w));
    }
    __syncwarp();

    int g = lane >> 2, t = lane & 3;
    float c[2][8][4];
#pragma unroll
    for (int tt = 0; tt < 2; tt++)
#pragma unroll
        for (int nt = 0; nt < 8; nt++) {
            float b0 = bs[nt * 8 + t * 2], b1 = bs[nt * 8 + t * 2 + 1];
            c[tt][nt][0] = b0; c[tt][nt][1] = b1; c[tt][nt][2] = b0; c[tt][nt][3] = b1;
        }

#pragma unroll
    for (int kt = 0; kt < 8; kt++) {
        uint32_t B0[8], B1[8];
#pragma unroll
        for (int nt = 0; nt < 8; nt++) {
            B0[nt] = Ws[(nt * 8 + g) * WSTRIDE + kt * 8 + t];
            B1[nt] = Ws[(nt * 8 + g) * WSTRIDE + kt * 8 + t + 4];
        }
#pragma unroll
        for (int tt = 0; tt < 2; tt++) {
            int rb = tt * 16;
            uint32_t a0 = myA[(rb + g) * WSTRIDE + kt * 8 + t];
            uint32_t a1 = myA[(rb + g + 8) * WSTRIDE + kt * 8 + t];
            uint32_t a2 = myA[(rb + g) * WSTRIDE + kt * 8 + t + 4];
            uint32_t a3 = myA[(rb + g + 8) * WSTRIDE + kt * 8 + t + 4];
#pragma unroll
            for (int nt = 0; nt < 8; nt++)
                mma_tf32(c[tt][nt], a0, a1, a2, a3, B0[nt], B1[nt]);
        }
    }

    __syncwarp();
#pragma unroll
    for (int tt = 0; tt < 2; tt++)
#pragma unroll
        for (int nt = 0; nt < 8; nt++) {
            myA[(tt * 16 + g) * CSTRIDE + nt * 4 + t]     = f2_to_bf(c[tt][nt][0], c[tt][nt][1]);
            myA[(tt * 16 + g + 8) * CSTRIDE + nt * 4 + t] = f2_to_bf(c[tt][nt][2], c[tt][nt][3]);
        }
    __syncwarp();
#pragma unroll
    for (int r = 0; r < 32; r++)
        g_xt_h[(long)(row0 + r) * 32 + lane] = myA[r * CSTRIDE + lane];
}

// ---------------- k_edge: m_e = binv * sum_{v in e} xt_v (bf16 gather, MLP-8) ----------------
__global__ void __launch_bounds__(256) k_edge() {
    int lane = threadIdx.x & 31;
    int e = blockIdx.x * 8 + (threadIdx.x >> 5);   // grid exact: N_HEDGES/8

    int end = g_colptr[e];
    int beg = (e == 0) ? 0 : g_colptr[e - 1];
    float2 acc = make_float2(0.f, 0.f);
    for (int chunk = beg; chunk < end; chunk += 32) {
        int n = min(32, end - chunk);
        int idx = (lane < n) ? g_csrE[chunk + lane] : 0;
        int k = 0;
        for (; k + 8 <= n; k += 8) {
            float2 f[8];
#pragma unroll
            for (int u = 0; u < 8; u++) {
                int v = __shfl_sync(FULLM, idx, k + u);
                f[u] = bf_to_f2(g_xt_h[(long)v * 32 + lane]);
            }
#pragma unroll
            for (int u = 0; u < 8; u++) { acc.x += f[u].x; acc.y += f[u].y; }
        }
        for (; k < n; k++) {
            int v = __shfl_sync(FULLM, idx, k);
            float2 f = bf_to_f2(g_xt_h[(long)v * 32 + lane]);
            acc.x += f.x;
            acc.y += f.y;
        }
    }
    int deg = end - beg;
    float bi = deg > 0 ? 1.f / (float)deg : 0.f;
    g_m_h[(long)e * 32 + lane] = f2_to_bf(acc.x * bi, acc.y * bi);
}

// ---------------- k_node: gather m_h (MLP-4) -> relu -> mma -> staged bf16 store ----------------
__global__ void __launch_bounds__(128) k_node(const float* __restrict__ W,
                                              const float* __restrict__ b) {
    __shared__ uint32_t Ws[CH * WSTRIDE];
    __shared__ float bs[CH];
    __shared__ uint32_t As[4][16 * WSTRIDE];
    for (int i = threadIdx.x; i < CH * CH; i += 128) {
        int k = i >> 6, n = i & 63;
        Ws[n * WSTRIDE + k] = tf32r(W[i]);
    }
    if (threadIdx.x < CH) bs[threadIdx.x] = b[threadIdx.x];
    __syncthreads();

    int lane = threadIdx.x & 31;
    int wid = threadIdx.x >> 5;
    int tile = blockIdx.x * 4 + wid;
    if (tile >= N_TILES) return;
    int row0 = tile * 16;
    uint32_t* myA = As[wid];

    for (int n = 0; n < 16; n++) {
        int v = row0 + n;
        int end = g_rowptr[v];
        int j = (v == 0) ? 0 : g_rowptr[v - 1];
        int deg = end - j;
        float2 acc = make_float2(0.f, 0.f);
        for (; j + 4 <= end; j += 4) {
            int e0 = g_csr[j], e1 = g_csr[j + 1], e2 = g_csr[j + 2], e3 = g_csr[j + 3];
            uint32_t p0 = g_m_h[(long)e0 * 32 + lane];
            uint32_t p1 = g_m_h[(long)e1 * 32 + lane];
            uint32_t p2 = g_m_h[(long)e2 * 32 + lane];
            uint32_t p3 = g_m_h[(long)e3 * 32 + lane];
            float2 f0 = bf_to_f2(p0), f1 = bf_to_f2(p1);
            float2 f2 = bf_to_f2(p2), f3 = bf_to_f2(p3);
            acc.x += (f0.x + f1.x) + (f2.x + f3.x);
            acc.y += (f0.y + f1.y) + (f2.y + f3.y);
        }
        for (; j < end; j++) {
            int e = g_csr[j];
            float2 f = bf_to_f2(g_m_h[(long)e * 32 + lane]);
            acc.x += f.x;
            acc.y += f.y;
        }
        float di = deg > 0 ? 1.f / (float)deg : 0.f;
        uint32_t h0 = tf32r(fmaxf(acc.x * di, 0.f));
        uint32_t h1 = tf32r(fmaxf(acc.y * di, 0.f));
        *(uint2*)&myA[n * WSTRIDE + 2 * lane] = make_uint2(h0, h1);
    }
    __syncwarp();

    int g = lane >> 2, t = lane & 3;
    float c[8][4];
#pragma unroll
    for (int nt = 0; nt < 8; nt++) {
        float b0 = bs[nt * 8 + t * 2], b1 = bs[nt * 8 + t * 2 + 1];
        c[nt][0] = b0; c[nt][1] = b1; c[nt][2] = b0; c[nt][3] = b1;
    }
#pragma unroll
    for (int kt = 0; kt < 8; kt++) {
        uint32_t a0 = myA[g * WSTRIDE + kt * 8 + t];
        uint32_t a1 = myA[(g + 8) * WSTRIDE + kt * 8 + t];
        uint32_t a2 = myA[g * WSTRIDE + kt * 8 + t + 4];
        uint32_t a3 = myA[(g + 8) * WSTRIDE + kt * 8 + t + 4];
#pragma unroll
        for (int nt = 0; nt < 8; nt++) {
            uint32_t b0 = Ws[(nt * 8 + g) * WSTRIDE + kt * 8 + t];
            uint32_t b1 = Ws[(nt * 8 + g) * WSTRIDE + kt * 8 + t + 4];
            mma_tf32(c[nt], a0, a1, a2, a3, b0, b1);
        }
    }

    __syncwarp();
#pragma unroll
    for (int nt = 0; nt < 8; nt++) {
        myA[g * CSTRIDE + nt * 4 + t]       = f2_to_bf(c[nt][0], c[nt][1]);
        myA[(g + 8) * CSTRIDE + nt * 4 + t] = f2_to_bf(c[nt][2], c[nt][3]);
    }
    __syncwarp();
#pragma unroll
    for (int r = 0; r < 16; r++)
        g_xt_h[(long)(row0 + r) * 32 + lane] = myA[r * CSTRIDE + lane];
}

// ---------------- conv2 pass B + pooling + fc dot (MLP-2) ----------------
__global__ void __launch_bounds__(256) k_conv_c(const int* __restrict__ batch,
                                                const float* __restrict__ Wfc) {
    int lane = threadIdx.x & 31;
    int warp = blockIdx.x * 8 + (threadIdx.x >> 5);
    int base = warp * 4;
    int grp = lane >> 4, c4 = (lane & 15) * 4;
    float4 wf = *(const float4*)(Wfc + c4);

    float acc = 0.f;
    int curg = -1;
#pragma unroll
    for (int n = 0; n < 4; n++) {
        int v = base + n;
        int end = g_rowptr[v];
        int beg = (v == 0) ? 0 : g_rowptr[v - 1];
        int deg = end - beg;
        float4 s = make_float4(0.f, 0.f, 0.f, 0.f);
        int j = grp;
        for (; j + 2 < deg; j += 4) {
            int e0 = g_csr[beg + j];
            int e1 = g_csr[beg + j + 2];
            uint2 p0 = *(const uint2*)(g_m_h + (long)e0 * 32 + (c4 >> 1));
            uint2 p1 = *(const uint2*)(g_m_h + (long)e1 * 32 + (c4 >> 1));
            float2 l0 = bf_to_f2(p0.x), h0 = bf_to_f2(p0.y);
            float2 l1 = bf_to_f2(p1.x), h1 = bf_to_f2(p1.y);
            s.x += l0.x + l1.x; s.y += l0.y + l1.y;
            s.z += h0.x + h1.x; s.w += h0.y + h1.y;
        }
        if (j < deg) {
            int e = g_csr[beg + j];
            uint2 pw = *(const uint2*)(g_m_h + (long)e * 32 + (c4 >> 1));
            float2 lo = bf_to_f2(pw.x), hi = bf_to_f2(pw.y);
            s.x += lo.x; s.y += lo.y; s.z += hi.x; s.w += hi.y;
        }
        s.x += __shfl_xor_sync(FULLM, s.x, 16);
        s.y += __shfl_xor_sync(FULLM, s.y, 16);
        s.z += __shfl_xor_sync(FULLM, s.z, 16);
        s.w += __shfl_xor_sync(FULLM, s.w, 16);
        float di = deg > 0 ? 1.f / (float)deg : 0.f;
        float p = 0.f;
        if (grp == 0) {
            p = fmaxf(di * s.x, 0.f) * wf.x + fmaxf(di * s.y, 0.f) * wf.y +
                fmaxf(di * s.z, 0.f) * wf.z + fmaxf(di * s.w, 0.f) * wf.w;
        }
#pragma unroll
        for (int o = 16; o > 0; o >>= 1) p += __shfl_xor_sync(FULLM, p, o);
        if (lane == 0) {
            int g = batch[v];
            if (g != curg) {
                if (curg >= 0) atomicAdd(&g_gsum[curg], acc);
                curg = g;
                acc = 0.f;
            }
            acc += p;
        }
    }
    if (lane == 0 && curg >= 0) atomicAdd(&g_gsum[curg], acc);
}

// ---------------- finalize ----------------
__global__ void k_fin(float* __restrict__ out, const float* __restrict__ bfc) {
    int g = blockIdx.x * blockDim.x + threadIdx.x;
    if (g < N_GRAPHS) {
        float cnt = fmaxf((float)g_gcnt[g], 1.f);
        out[g] = g_gsum[g] / cnt + bfc[0];
    }
}

// ---------------- launch ----------------
extern "C" void kernel_launch(void* const* d_in, const int* in_sizes, int n_in,
                              void* d_out, int out_size) {
    const float* x     = (const float*)d_in[0];
    const int*   eidx  = (const int*)d_in[1];
    const int*   row   = eidx;
    const int*   col   = eidx + N_INC;
    const int*   batch = (const int*)d_in[2];
    const float* W1    = (const float*)d_in[3];
    const float* b1    = (const float*)d_in[4];
    const float* W2    = (const float*)d_in[5];
    const float* b2    = (const float*)d_in[6];
    const float* Wfc   = (const float*)d_in[7];
    const float* bfc   = (const float*)d_in[8];
    float*       out   = (float*)d_out;

    const int XT_SMEM  = (CH * WSTRIDE + 4 * 32 * WSTRIDE) * 4;   // 52224 B
    static bool attr_done = false;
    if (!attr_done) {
        cudaFuncSetAttribute(k_xt, cudaFuncAttributeMaxDynamicSharedMemorySize, XT_SMEM);
        attr_done = true;
    }

    const int NB_INC   = (N_INC + 255) / 256;          // 7813
    const int NB_XT    = (N_TILES / 2 + 3) / 4;        // 3907
    const int NB_MM    = (N_TILES + 3) / 4;            // 7813
    const int NB_EDGE  = N_HEDGES / 8;                 // 12500
    const int NB_CONVC = (N_NODES / 4) / 8;            // 15625

    k_zero<<<512, 256>>>();
    k_hist<<<NB_INC, 256>>>(row, col, batch);
    k_scan<<<NB_SCANT, 1024>>>();
    k_fill<<<NB_INC, 256>>>(row, col);     // position 4 -> gets the ncu capture
    k_xt<<<NB_XT, 128, XT_SMEM>>>(x, W1, b1);
    k_edge<<<NB_EDGE, 256>>>();
    k_node<<<NB_MM, 128>>>(W2, b2);
    k_edge<<<NB_EDGE, 256>>>();
    k_conv_c<<<NB_CONVC, 256>>>(batch, Wfc);
    k_fin<<<2, 256>>>(out, bfc);
}

// round 12
// speedup vs baseline: 1.0580x; 1.0580x over previous
#include <cuda_runtime.h>
#include <cuda_bf16.h>
#include <cstdint>

#define N_NODES     500000
#define N_INC       2000000
#define N_HEDGES    100000
#define N_GRAPHS    512
#define CH          64
#define FULLM       0xffffffffu
#define N_TILES     31250          // N_NODES / 16 (even)
#define WSTRIDE     68             // padded smem row stride for A/W tiles
#define CSTRIDE     36             // C-stage stride: bank=(4r+c)%32 conflict-free
#define NB_SCANN    489            // ceil(N_NODES/1024)
#define NB_SCANE    98             // ceil(N_HEDGES/1024)
#define NB_SCANT    (NB_SCANN + NB_SCANE)   // 587

// ---------------- scratch (device globals; no allocation allowed) ----------------
__device__ __align__(256) uint32_t g_xt_h[(long)N_NODES * 32];   // 64 MB bf16 rows (128B each)
__device__ __align__(256) uint32_t g_m_h [(long)N_HEDGES * 32];  // 12.8 MB bf16 rows
__device__ int   g_degN[N_NODES];
__device__ int   g_degE[N_HEDGES];
__device__ int   g_rowptr[N_NODES];         // after fill: rowptr[v] = END of node v's segment
__device__ int   g_colptr[N_HEDGES];        // after fill: colptr[e] = END of edge e's segment
__device__ int   g_csr[N_INC];              // edge ids, grouped by node
__device__ int   g_csrE[N_INC];             // node ids, grouped by edge
__device__ int   g_agg [NB_SCANT];          // decoupled-lookback aggregates
__device__ int   g_pref[NB_SCANT];          // inclusive prefixes
__device__ int   g_stat[NB_SCANT];          // 0 invalid / 1 agg / 2 prefix
__device__ float g_gsum[N_GRAPHS];
__device__ int   g_gcnt[N_GRAPHS];

// ---------------- small helpers ----------------
__device__ __forceinline__ uint32_t f2_to_bf(float a, float b) {
    uint32_t r;
    asm("cvt.rn.bf16x2.f32 %0, %1, %2;" : "=r"(r) : "f"(b), "f"(a));
    return r;
}
__device__ __forceinline__ float2 bf_to_f2(uint32_t p) {
    return __bfloat1622float2(*reinterpret_cast<const __nv_bfloat162*>(&p));
}
__device__ __forceinline__ uint32_t tf32r(float f) {
    uint32_t r;
    asm("cvt.rna.tf32.f32 %0, %1;" : "=r"(r) : "f"(f));
    return r;
}
__device__ __forceinline__ void mma_tf32(float c[4],
                                         uint32_t a0, uint32_t a1, uint32_t a2, uint32_t a3,
                                         uint32_t b0, uint32_t b1) {
    asm volatile("mma.sync.aligned.m16n8k8.row.col.f32.tf32.tf32.f32 "
                 "{%0,%1,%2,%3}, {%4,%5,%6,%7}, {%8,%9}, {%0,%1,%2,%3};"
                 : "+f"(c[0]), "+f"(c[1]), "+f"(c[2]), "+f"(c[3])
                 : "r"(a0), "r"(a1), "r"(a2), "r"(a3), "r"(b0), "r"(b1));
}

// ---------------- zero scratch ----------------
__global__ void k_zero() {
    int t = blockIdx.x * blockDim.x + threadIdx.x;
    int S = gridDim.x * blockDim.x;
    for (int j = t; j < N_NODES; j += S) g_degN[j] = 0;
    for (int j = t; j < N_HEDGES; j += S) g_degE[j] = 0;
    for (int j = t; j < N_GRAPHS; j += S) { g_gsum[j] = 0.f; g_gcnt[j] = 0; }
    for (int j = t; j < NB_SCANT; j += S) g_stat[j] = 0;
}

// ---------------- degree histograms + graph-size histogram ----------------
__global__ void k_hist(const int* __restrict__ row, const int* __restrict__ col,
                       const int* __restrict__ batch) {
    int i = blockIdx.x * blockDim.x + threadIdx.x;
    if (i < N_INC) {
        atomicAdd(&g_degN[row[i]], 1);
        atomicAdd(&g_degE[col[i]], 1);
    }
    unsigned act = __ballot_sync(FULLM, i < N_NODES);
    if (i < N_NODES) {
        int g = batch[i];
        unsigned mask = __match_any_sync(act, g);
        int leader = __ffs(mask) - 1;
        if ((threadIdx.x & 31) == leader) atomicAdd(&g_gcnt[g], __popc(mask));
    }
}

// ---------------- single-kernel exclusive scans, WARP-PARALLEL decoupled lookback ----------------
// Two chains: node blocks [0, NB_SCANN), edge blocks [NB_SCANN, NB_SCANT).
// Warp 31 scans 32 predecessors per window; p < chainStart acts as a zero prefix,
// so lookback never crosses chains. (Round 11's single-thread lookback serialized
// ~489 dependent L2 round-trips = the +63 us regression.)
__global__ void k_scan() {
    int mode = blockIdx.x >= NB_SCANN;
    int blk = mode ? blockIdx.x - NB_SCANN : blockIdx.x;
    const int* __restrict__ in = mode ? g_degE : g_degN;
    int* __restrict__ out = mode ? g_colptr : g_rowptr;
    int n = mode ? N_HEDGES : N_NODES;
    int gix = blockIdx.x;

    __shared__ int sh[1024];
    __shared__ int s_off;
    int tid = threadIdx.x;
    int i = blk * 1024 + tid;
    int v = (i < n) ? in[i] : 0;
    sh[tid] = v;
    __syncthreads();
#pragma unroll
    for (int off = 1; off < 1024; off <<= 1) {
        int t = (tid >= off) ? sh[tid - off] : 0;
        __syncthreads();
        sh[tid] += t;
        __syncthreads();
    }

    if (tid >= 992) {                 // warp 31
        int lane = tid - 992;
        int total = sh[1023];
        if (blk == 0) {
            if (lane == 0) {
                g_pref[gix] = total;
                __threadfence();
                g_stat[gix] = 2;
                s_off = 0;
            }
        } else {
            if (lane == 0) {
                g_agg[gix] = total;
                __threadfence();
                g_stat[gix] = 1;
            }
            __syncwarp();
            int chainStart = gix - blk;
            int sum = 0;
            int base = gix - 1;
            while (true) {
                int p = base - lane;
                int st, val;
                if (p < chainStart) {
                    st = 2; val = 0;
                } else {
                    do { st = ((volatile int*)g_stat)[p]; } while (st == 0);
                    __threadfence();
                    val = (st == 2) ? ((volatile int*)g_pref)[p]
                                    : ((volatile int*)g_agg)[p];
                }
                unsigned pm = __ballot_sync(FULLM, st == 2);
                int firstp = __ffs(pm) - 1;       // nearest prefix lane (pm may be 0)
                int contrib = pm ? ((lane <= firstp) ? val : 0) : val;
#pragma unroll
                for (int o2 = 16; o2; o2 >>= 1)
                    contrib += __shfl_xor_sync(FULLM, contrib, o2);
                sum += contrib;
                if (pm) break;
                base -= 32;
            }
            if (lane == 0) {
                g_pref[gix] = sum + total;
                __threadfence();
                g_stat[gix] = 2;
                s_off = sum;
            }
        }
    }
    __syncthreads();
    if (i < n) out[i] = s_off + sh[tid] - v;   // exclusive prefix
}

// ---------------- fill both CSRs (atomicAdd directly on the ptr arrays) ----------------
// After this kernel ptr[v] = END of v's segment; beg(v) = v ? ptr[v-1] : 0.
__global__ void k_fill(const int* __restrict__ row, const int* __restrict__ col) {
    int i = blockIdx.x * blockDim.x + threadIdx.x;
    if (i < N_INC) {
        int r = row[i], c = col[i];
        int pr = atomicAdd(&g_rowptr[r], 1);
        g_csr[pr] = c;
        int pc = atomicAdd(&g_colptr[c], 1);
        g_csrE[pc] = r;
    }
}

// ---------------- k_xt: xt = x W1 + b1 via tf32 mma ----------------
extern __shared__ uint32_t xt_smem[];
__global__ void __launch_bounds__(128) k_xt(const float* __restrict__ x,
                                            const float* __restrict__ W,
                                            const float* __restrict__ b) {
    uint32_t* Ws = xt_smem;                       // tf32 bits, [n][k] stride 68
    __shared__ float bs[CH];
    for (int i = threadIdx.x; i < CH * CH; i += 128) {
        int k = i >> 6, n = i & 63;
        Ws[n * WSTRIDE + k] = tf32r(W[i]);
    }
    if (threadIdx.x < CH) bs[threadIdx.x] = b[threadIdx.x];
    __syncthreads();

    int lane = threadIdx.x & 31;
    int wid = threadIdx.x >> 5;
    int wg = blockIdx.x * 4 + wid;
    int tileBase = wg * 2;
    if (tileBase >= N_TILES) return;   // N_TILES even -> both tiles valid
    int row0 = tileBase * 16;
    uint32_t* myA = xt_smem + CH * WSTRIDE + wid * (32 * WSTRIDE);

    const float* xbase = x + (long)row0 * CH;
#pragma unroll
    for (int i = 0; i < 16; i++) {
        int idx = i * 32 + lane;
        int r = idx >> 4, c4 = (idx & 15) * 4;
        float4 v = *(const float4*)(xbase + r * CH + c4);
        *(uint4*)&myA[r * WSTRIDE + c4] =
            make_uint4(tf32r(v.x), tf32r(v.y), tf32r(v.z), tf32r(v.w));
    }
    __syncwarp();

    int g = lane >> 2, t = lane & 3;
    float c[2][8][4];
#pragma unroll
    for (int tt = 0; tt < 2; tt++)
#pragma unroll
        for (int nt = 0; nt < 8; nt++) {
            float b0 = bs[nt * 8 + t * 2], b1 = bs[nt * 8 + t * 2 + 1];
            c[tt][nt][0] = b0; c[tt][nt][1] = b1; c[tt][nt][2] = b0; c[tt][nt][3] = b1;
        }

#pragma unroll
    for (int kt = 0; kt < 8; kt++) {
        uint32_t B0[8], B1[8];
#pragma unroll
        for (int nt = 0; nt < 8; nt++) {
            B0[nt] = Ws[(nt * 8 + g) * WSTRIDE + kt * 8 + t];
            B1[nt] = Ws[(nt * 8 + g) * WSTRIDE + kt * 8 + t + 4];
        }
#pragma unroll
        for (int tt = 0; tt < 2; tt++) {
            int rb = tt * 16;
            uint32_t a0 = myA[(rb + g) * WSTRIDE + kt * 8 + t];
            uint32_t a1 = myA[(rb + g + 8) * WSTRIDE + kt * 8 + t];
            uint32_t a2 = myA[(rb + g) * WSTRIDE + kt * 8 + t + 4];
            uint32_t a3 = myA[(rb + g + 8) * WSTRIDE + kt * 8 + t + 4];
#pragma unroll
            for (int nt = 0; nt < 8; nt++)
                mma_tf32(c[tt][nt], a0, a1, a2, a3, B0[nt], B1[nt]);
        }
    }

    __syncwarp();
#pragma unroll
    for (int tt = 0; tt < 2; tt++)
#pragma unroll
        for (int nt = 0; nt < 8; nt++) {
            myA[(tt * 16 + g) * CSTRIDE + nt * 4 + t]     = f2_to_bf(c[tt][nt][0], c[tt][nt][1]);
            myA[(tt * 16 + g + 8) * CSTRIDE + nt * 4 + t] = f2_to_bf(c[tt][nt][2], c[tt][nt][3]);
        }
    __syncwarp();
#pragma unroll
    for (int r = 0; r < 32; r++)
        g_xt_h[(long)(row0 + r) * 32 + lane] = myA[r * CSTRIDE + lane];
}

// ---------------- k_edge: m_e = binv * sum_{v in e} xt_v (bf16 gather, MLP-8) ----------------
__global__ void __launch_bounds__(256) k_edge() {
    int lane = threadIdx.x & 31;
    int e = blockIdx.x * 8 + (threadIdx.x >> 5);   // grid exact: N_HEDGES/8

    int end = g_colptr[e];
    int beg = (e == 0) ? 0 : g_colptr[e - 1];
    float2 acc = make_float2(0.f, 0.f);
    for (int chunk = beg; chunk < end; chunk += 32) {
        int n = min(32, end - chunk);
        int idx = (lane < n) ? g_csrE[chunk + lane] : 0;
        int k = 0;
        for (; k + 8 <= n; k += 8) {
            float2 f[8];
#pragma unroll
            for (int u = 0; u < 8; u++) {
                int v = __shfl_sync(FULLM, idx, k + u);
                f[u] = bf_to_f2(g_xt_h[(long)v * 32 + lane]);
            }
#pragma unroll
            for (int u = 0; u < 8; u++) { acc.x += f[u].x; acc.y += f[u].y; }
        }
        for (; k < n; k++) {
            int v = __shfl_sync(FULLM, idx, k);
            float2 f = bf_to_f2(g_xt_h[(long)v * 32 + lane]);
            acc.x += f.x;
            acc.y += f.y;
        }
    }
    int deg = end - beg;
    float bi = deg > 0 ? 1.f / (float)deg : 0.f;
    g_m_h[(long)e * 32 + lane] = f2_to_bf(acc.x * bi, acc.y * bi);
}

// ---------------- k_node: gather m_h (MLP-4) -> relu -> mma -> staged bf16 store ----------------
__global__ void __launch_bounds__(128) k_node(const float* __restrict__ W,
                                              const float* __restrict__ b) {
    __shared__ uint32_t Ws[CH * WSTRIDE];
    __shared__ float bs[CH];
    __shared__ uint32_t As[4][16 * WSTRIDE];
    for (int i = threadIdx.x; i < CH * CH; i += 128) {
        int k = i >> 6, n = i & 63;
        Ws[n * WSTRIDE + k] = tf32r(W[i]);
    }
    if (threadIdx.x < CH) bs[threadIdx.x] = b[threadIdx.x];
    __syncthreads();

    int lane = threadIdx.x & 31;
    int wid = threadIdx.x >> 5;
    int tile = blockIdx.x * 4 + wid;
    if (tile >= N_TILES) return;
    int row0 = tile * 16;
    uint32_t* myA = As[wid];

    for (int n = 0; n < 16; n++) {
        int v = row0 + n;
        int end = g_rowptr[v];
        int j = (v == 0) ? 0 : g_rowptr[v - 1];
        int deg = end - j;
        float2 acc = make_float2(0.f, 0.f);
        for (; j + 4 <= end; j += 4) {
            int e0 = g_csr[j], e1 = g_csr[j + 1], e2 = g_csr[j + 2], e3 = g_csr[j + 3];
            uint32_t p0 = g_m_h[(long)e0 * 32 + lane];
            uint32_t p1 = g_m_h[(long)e1 * 32 + lane];
            uint32_t p2 = g_m_h[(long)e2 * 32 + lane];
            uint32_t p3 = g_m_h[(long)e3 * 32 + lane];
            float2 f0 = bf_to_f2(p0), f1 = bf_to_f2(p1);
            float2 f2 = bf_to_f2(p2), f3 = bf_to_f2(p3);
            acc.x += (f0.x + f1.x) + (f2.x + f3.x);
            acc.y += (f0.y + f1.y) + (f2.y + f3.y);
        }
        for (; j < end; j++) {
            int e = g_csr[j];
            float2 f = bf_to_f2(g_m_h[(long)e * 32 + lane]);
            acc.x += f.x;
            acc.y += f.y;
        }
        float di = deg > 0 ? 1.f / (float)deg : 0.f;
        uint32_t h0 = tf32r(fmaxf(acc.x * di, 0.f));
        uint32_t h1 = tf32r(fmaxf(acc.y * di, 0.f));
        *(uint2*)&myA[n * WSTRIDE + 2 * lane] = make_uint2(h0, h1);
    }
    __syncwarp();

    int g = lane >> 2, t = lane & 3;
    float c[8][4];
#pragma unroll
    for (int nt = 0; nt < 8; nt++) {
        float b0 = bs[nt * 8 + t * 2], b1 = bs[nt * 8 + t * 2 + 1];
        c[nt][0] = b0; c[nt][1] = b1; c[nt][2] = b0; c[nt][3] = b1;
    }
#pragma unroll
    for (int kt = 0; kt < 8; kt++) {
        uint32_t a0 = myA[g * WSTRIDE + kt * 8 + t];
        uint32_t a1 = myA[(g + 8) * WSTRIDE + kt * 8 + t];
        uint32_t a2 = myA[g * WSTRIDE + kt * 8 + t + 4];
        uint32_t a3 = myA[(g + 8) * WSTRIDE + kt * 8 + t + 4];
#pragma unroll
        for (int nt = 0; nt < 8; nt++) {
            uint32_t b0 = Ws[(nt * 8 + g) * WSTRIDE + kt * 8 + t];
            uint32_t b1 = Ws[(nt * 8 + g) * WSTRIDE + kt * 8 + t + 4];
            mma_tf32(c[nt], a0, a1, a2, a3, b0, b1);
        }
    }

    __syncwarp();
#pragma unroll
    for (int nt = 0; nt < 8; nt++) {
        myA[g * CSTRIDE + nt * 4 + t]       = f2_to_bf(c[nt][0], c[nt][1]);
        myA[(g + 8) * CSTRIDE + nt * 4 + t] = f2_to_bf(c[nt][2], c[nt][3]);
    }
    __syncwarp();
#pragma unroll
    for (int r = 0; r < 16; r++)
        g_xt_h[(long)(row0 + r) * 32 + lane] = myA[r * CSTRIDE + lane];
}

// ---------------- conv2 pass B + pooling + fc dot (MLP-2) ----------------
__global__ void __launch_bounds__(256) k_conv_c(const int* __restrict__ batch,
                                                const float* __restrict__ Wfc) {
    int lane = threadIdx.x & 31;
    int warp = blockIdx.x * 8 + (threadIdx.x >> 5);
    int base = warp * 4;
    int grp = lane >> 4, c4 = (lane & 15) * 4;
    float4 wf = *(const float4*)(Wfc + c4);

    float acc = 0.f;
    int curg = -1;
#pragma unroll
    for (int n = 0; n < 4; n++) {
        int v = base + n;
        int end = g_rowptr[v];
        int beg = (v == 0) ? 0 : g_rowptr[v - 1];
        int deg = end - beg;
        float4 s = make_float4(0.f, 0.f, 0.f, 0.f);
        int j = grp;
        for (; j + 2 < deg; j += 4) {
            int e0 = g_csr[beg + j];
            int e1 = g_csr[beg + j + 2];
            uint2 p0 = *(const uint2*)(g_m_h + (long)e0 * 32 + (c4 >> 1));
            uint2 p1 = *(const uint2*)(g_m_h + (long)e1 * 32 + (c4 >> 1));
            float2 l0 = bf_to_f2(p0.x), h0 = bf_to_f2(p0.y);
            float2 l1 = bf_to_f2(p1.x), h1 = bf_to_f2(p1.y);
            s.x += l0.x + l1.x; s.y += l0.y + l1.y;
            s.z += h0.x + h1.x; s.w += h0.y + h1.y;
        }
        if (j < deg) {
            int e = g_csr[beg + j];
            uint2 pw = *(const uint2*)(g_m_h + (long)e * 32 + (c4 >> 1));
            float2 lo = bf_to_f2(pw.x), hi = bf_to_f2(pw.y);
            s.x += lo.x; s.y += lo.y; s.z += hi.x; s.w += hi.y;
        }
        s.x += __shfl_xor_sync(FULLM, s.x, 16);
        s.y += __shfl_xor_sync(FULLM, s.y, 16);
        s.z += __shfl_xor_sync(FULLM, s.z, 16);
        s.w += __shfl_xor_sync(FULLM, s.w, 16);
        float di = deg > 0 ? 1.f / (float)deg : 0.f;
        float p = 0.f;
        if (grp == 0) {
            p = fmaxf(di * s.x, 0.f) * wf.x + fmaxf(di * s.y, 0.f) * wf.y +
                fmaxf(di * s.z, 0.f) * wf.z + fmaxf(di * s.w, 0.f) * wf.w;
        }
#pragma unroll
        for (int o = 16; o > 0; o >>= 1) p += __shfl_xor_sync(FULLM, p, o);
        if (lane == 0) {
            int g = batch[v];
            if (g != curg) {
                if (curg >= 0) atomicAdd(&g_gsum[curg], acc);
                curg = g;
                acc = 0.f;
            }
            acc += p;
        }
    }
    if (lane == 0 && curg >= 0) atomicAdd(&g_gsum[curg], acc);
}

// ---------------- finalize ----------------
__global__ void k_fin(float* __restrict__ out, const float* __restrict__ bfc) {
    int g = blockIdx.x * blockDim.x + threadIdx.x;
    if (g < N_GRAPHS) {
        float cnt = fmaxf((float)g_gcnt[g], 1.f);
        out[g] = g_gsum[g] / cnt + bfc[0];
    }
}

// ---------------- launch ----------------
extern "C" void kernel_launch(void* const* d_in, const int* in_sizes, int n_in,
                              void* d_out, int out_size) {
    const float* x     = (const float*)d_in[0];
    const int*   eidx  = (const int*)d_in[1];
    const int*   row   = eidx;
    const int*   col   = eidx + N_INC;
    const int*   batch = (const int*)d_in[2];
    const float* W1    = (const float*)d_in[3];
    const float* b1    = (const float*)d_in[4];
    const float* W2    = (const float*)d_in[5];
    const float* b2    = (const float*)d_in[6];
    const float* Wfc   = (const float*)d_in[7];
    const float* bfc   = (const float*)d_in[8];
    float*       out   = (float*)d_out;

    const int XT_SMEM  = (CH * WSTRIDE + 4 * 32 * WSTRIDE) * 4;   // 52224 B
    static bool attr_done = false;
    if (!attr_done) {
        cudaFuncSetAttribute(k_xt, cudaFuncAttributeMaxDynamicSharedMemorySize, XT_SMEM);
        attr_done = true;
    }

    const int NB_INC   = (N_INC + 255) / 256;          // 7813
    const int NB_XT    = (N_TILES / 2 + 3) / 4;        // 3907
    const int NB_MM    = (N_TILES + 3) / 4;            // 7813
    const int NB_EDGE  = N_HEDGES / 8;                 // 12500
    const int NB_CONVC = (N_NODES / 4) / 8;            // 15625

    k_zero<<<512, 256>>>();
    k_hist<<<NB_INC, 256>>>(row, col, batch);
    k_xt<<<NB_XT, 128, XT_SMEM>>>(x, W1, b1);
    k_scan<<<NB_SCANT, 1024>>>();          // position 4 -> gets the ncu capture
    k_fill<<<NB_INC, 256>>>(row, col);
    k_edge<<<NB_EDGE, 256>>>();
    k_node<<<NB_MM, 128>>>(W2, b2);
    k_edge<<<NB_EDGE, 256>>>();
    k_conv_c<<<NB_CONVC, 256>>>(batch, Wfc);
    k_fin<<<2, 256>>>(out, bfc);
}

// round 13
// speedup vs baseline: 1.0948x; 1.0347x over previous
#include <cuda_runtime.h>
#include <cuda_bf16.h>
#include <cstdint>

#define N_NODES     500000
#define N_INC       2000000
#define HALF_INC    1000000
#define N_HEDGES    100000
#define N_GRAPHS    512
#define CH          64
#define FULLM       0xffffffffu
#define N_TILES     31250          // N_NODES / 16 (even)
#define WSTRIDE     68             // padded smem row stride for A/W tiles
#define CSTRIDE     36             // C-stage stride: bank=(4r+c)%32 conflict-free
#define NB_SCANN    489            // ceil(N_NODES/1024)
#define NB_SCANE    98             // ceil(N_HEDGES/1024)
#define NB_SCANT    (NB_SCANN + NB_SCANE)   // 587

// ---------------- scratch (device globals; no allocation allowed) ----------------
__device__ __align__(256) uint32_t g_xt_h[(long)N_NODES * 32];   // 64 MB bf16 rows (128B each)
__device__ __align__(256) uint32_t g_m_h [(long)N_HEDGES * 32];  // 12.8 MB bf16 rows
__device__ int   g_degN[N_NODES];
__device__ int   g_degE[N_HEDGES];
__device__ int   g_rowptr[N_NODES + 1];     // node -> edges (classic CSR)
__device__ int   g_colptr[N_HEDGES + 1];    // edge -> nodes
__device__ int   g_cursor[N_NODES];
__device__ int   g_cursorE[N_HEDGES];
__device__ int   g_csr[N_INC];              // edge ids, grouped by node
__device__ int   g_csrE[N_INC];             // node ids, grouped by edge
__device__ int   g_agg [NB_SCANT];          // decoupled-lookback aggregates
__device__ int   g_pref[NB_SCANT];          // inclusive prefixes
__device__ int   g_stat[NB_SCANT];          // 0 invalid / 1 agg / 2 prefix
__device__ float g_gsum[N_GRAPHS];
__device__ int   g_gcnt[N_GRAPHS];

// ---------------- small helpers ----------------
__device__ __forceinline__ uint32_t f2_to_bf(float a, float b) {
    uint32_t r;
    asm("cvt.rn.bf16x2.f32 %0, %1, %2;" : "=r"(r) : "f"(b), "f"(a));
    return r;
}
__device__ __forceinline__ float2 bf_to_f2(uint32_t p) {
    return __bfloat1622float2(*reinterpret_cast<const __nv_bfloat162*>(&p));
}
__device__ __forceinline__ uint32_t tf32r(float f) {
    uint32_t r;
    asm("cvt.rna.tf32.f32 %0, %1;" : "=r"(r) : "f"(f));
    return r;
}
__device__ __forceinline__ void mma_tf32(float c[4],
                                         uint32_t a0, uint32_t a1, uint32_t a2, uint32_t a3,
                                         uint32_t b0, uint32_t b1) {
    asm volatile("mma.sync.aligned.m16n8k8.row.col.f32.tf32.tf32.f32 "
                 "{%0,%1,%2,%3}, {%4,%5,%6,%7}, {%8,%9}, {%0,%1,%2,%3};"
                 : "+f"(c[0]), "+f"(c[1]), "+f"(c[2]), "+f"(c[3])
                 : "r"(a0), "r"(a1), "r"(a2), "r"(a3), "r"(b0), "r"(b1));
}

// ---------------- zero scratch (split so k_hist lands at capture position 4) ----------------
__global__ void k_zero1() {
    int t = blockIdx.x * blockDim.x + threadIdx.x;
    int S = gridDim.x * blockDim.x;
    for (int j = t; j < N_NODES; j += S) { g_degN[j] = 0; g_cursor[j] = 0; }
    for (int j = t; j < N_HEDGES; j += S) { g_degE[j] = 0; g_cursorE[j] = 0; }
}
__global__ void k_zero2() {
    int t = blockIdx.x * blockDim.x + threadIdx.x;
    int S = gridDim.x * blockDim.x;
    for (int j = t; j < N_GRAPHS; j += S) { g_gsum[j] = 0.f; g_gcnt[j] = 0; }
    for (int j = t; j < NB_SCANT; j += S) g_stat[j] = 0;
}

// ---------------- degree histograms + graph-size histogram (ILP-2 on incidences) ----------------
__global__ void k_hist(const int* __restrict__ row, const int* __restrict__ col,
                       const int* __restrict__ batch) {
    int i = blockIdx.x * blockDim.x + threadIdx.x;
    if (i < HALF_INC) {
        int r0 = row[i], c0 = col[i];
        int r1 = row[i + HALF_INC], c1 = col[i + HALF_INC];
        atomicAdd(&g_degN[r0], 1);
        atomicAdd(&g_degN[r1], 1);
        atomicAdd(&g_degE[c0], 1);
        atomicAdd(&g_degE[c1], 1);
    }
    unsigned act = __ballot_sync(FULLM, i < N_NODES);
    if (i < N_NODES) {
        int g = batch[i];
        unsigned mask = __match_any_sync(act, g);
        int leader = __ffs(mask) - 1;
        if ((threadIdx.x & 31) == leader) atomicAdd(&g_gcnt[g], __popc(mask));
    }
}

// ---------------- single-kernel exclusive scans, warp-parallel decoupled lookback ----------------
// (measured 21.7 us in round 12). Classic CSR output: out[i] = exclusive prefix,
// out[n] = N_INC terminator. Two chains; p < chainStart acts as a zero prefix.
__global__ void k_scan() {
    int mode = blockIdx.x >= NB_SCANN;
    int blk = mode ? blockIdx.x - NB_SCANN : blockIdx.x;
    const int* __restrict__ in = mode ? g_degE : g_degN;
    int* __restrict__ out = mode ? g_colptr : g_rowptr;
    int n = mode ? N_HEDGES : N_NODES;
    int gix = blockIdx.x;

    __shared__ int sh[1024];
    __shared__ int s_off;
    int tid = threadIdx.x;
    int i = blk * 1024 + tid;
    int v = (i < n) ? in[i] : 0;
    sh[tid] = v;
    __syncthreads();
#pragma unroll
    for (int off = 1; off < 1024; off <<= 1) {
        int t = (tid >= off) ? sh[tid - off] : 0;
        __syncthreads();
        sh[tid] += t;
        __syncthreads();
    }

    if (tid >= 992) {                 // warp 31
        int lane = tid - 992;
        int total = sh[1023];
        if (blk == 0) {
            if (lane == 0) {
                g_pref[gix] = total;
                __threadfence();
                g_stat[gix] = 2;
                s_off = 0;
            }
        } else {
            if (lane == 0) {
                g_agg[gix] = total;
                __threadfence();
                g_stat[gix] = 1;
            }
            __syncwarp();
            int chainStart = gix - blk;
            int sum = 0;
            int base = gix - 1;
            while (true) {
                int p = base - lane;
                int st, val;
                if (p < chainStart) {
                    st = 2; val = 0;
                } else {
                    do { st = ((volatile int*)g_stat)[p]; } while (st == 0);
                    __threadfence();
                    val = (st == 2) ? ((volatile int*)g_pref)[p]
                                    : ((volatile int*)g_agg)[p];
                }
                unsigned pm = __ballot_sync(FULLM, st == 2);
                int firstp = __ffs(pm) - 1;
                int contrib = pm ? ((lane <= firstp) ? val : 0) : val;
#pragma unroll
                for (int o2 = 16; o2; o2 >>= 1)
                    contrib += __shfl_xor_sync(FULLM, contrib, o2);
                sum += contrib;
                if (pm) break;
                base -= 32;
            }
            if (lane == 0) {
                g_pref[gix] = sum + total;
                __threadfence();
                g_stat[gix] = 2;
                s_off = sum;
            }
        }
    }
    __syncthreads();
    if (i < n) out[i] = s_off + sh[tid] - v;   // exclusive prefix
    if (i == 0) out[n] = N_INC;                // terminator (blk 0 of each chain)
}

// ---------------- fill both CSRs (ILP-2: 4 independent atomic chains per thread) ----------------
__global__ void k_fill(const int* __restrict__ row, const int* __restrict__ col) {
    int i = blockIdx.x * blockDim.x + threadIdx.x;
    if (i >= HALF_INC) return;
    int r0 = row[i], c0 = col[i];
    int r1 = row[i + HALF_INC], c1 = col[i + HALF_INC];
    int a0 = atomicAdd(&g_cursor[r0], 1);
    int a1 = atomicAdd(&g_cursor[r1], 1);
    int b0 = atomicAdd(&g_cursorE[c0], 1);
    int b1 = atomicAdd(&g_cursorE[c1], 1);
    g_csr[g_rowptr[r0] + a0] = c0;
    g_csr[g_rowptr[r1] + a1] = c1;
    g_csrE[g_colptr[c0] + b0] = r0;
    g_csrE[g_colptr[c1] + b1] = r1;
}

// ---------------- k_xt: xt = x W1 + b1 via tf32 mma (round-10 proven) ----------------
extern __shared__ uint32_t xt_smem[];
__global__ void __launch_bounds__(128) k_xt(const float* __restrict__ x,
                                            const float* __restrict__ W,
                                            const float* __restrict__ b) {
    uint32_t* Ws = xt_smem;                       // tf32 bits, [n][k] stride 68
    __shared__ float bs[CH];
    for (int i = threadIdx.x; i < CH * CH; i += 128) {
        int k = i >> 6, n = i & 63;
        Ws[n * WSTRIDE + k] = tf32r(W[i]);
    }
    if (threadIdx.x < CH) bs[threadIdx.x] = b[threadIdx.x];
    __syncthreads();

    int lane = threadIdx.x & 31;
    int wid = threadIdx.x >> 5;
    int wg = blockIdx.x * 4 + wid;
    int tileBase = wg * 2;
    if (tileBase >= N_TILES) return;
    int row0 = tileBase * 16;
    uint32_t* myA = xt_smem + CH * WSTRIDE + wid * (32 * WSTRIDE);

    const float* xbase = x + (long)row0 * CH;
#pragma unroll
    for (int i = 0; i < 16; i++) {
        int idx = i * 32 + lane;
        int r = idx >> 4, c4 = (idx & 15) * 4;
        float4 v = *(const float4*)(xbase + r * CH + c4);
        *(uint4*)&myA[r * WSTRIDE + c4] =
            make_uint4(tf32r(v.x), tf32r(v.y), tf32r(v.z), tf32r(v.w));
    }
    __syncwarp();

    int g = lane >> 2, t = lane & 3;
    float c[2][8][4];
#pragma unroll
    for (int tt = 0; tt < 2; tt++)
#pragma unroll
        for (int nt = 0; nt < 8; nt++) {
            float b0 = bs[nt * 8 + t * 2], b1 = bs[nt * 8 + t * 2 + 1];
            c[tt][nt][0] = b0; c[tt][nt][1] = b1; c[tt][nt][2] = b0; c[tt][nt][3] = b1;
        }

#pragma unroll
    for (int kt = 0; kt < 8; kt++) {
        uint32_t B0[8], B1[8];
#pragma unroll
        for (int nt = 0; nt < 8; nt++) {
            B0[nt] = Ws[(nt * 8 + g) * WSTRIDE + kt * 8 + t];
            B1[nt] = Ws[(nt * 8 + g) * WSTRIDE + kt * 8 + t + 4];
        }
#pragma unroll
        for (int tt = 0; tt < 2; tt++) {
            int rb = tt * 16;
            uint32_t a0 = myA[(rb + g) * WSTRIDE + kt * 8 + t];
            uint32_t a1 = myA[(rb + g + 8) * WSTRIDE + kt * 8 + t];
            uint32_t a2 = myA[(rb + g) * WSTRIDE + kt * 8 + t + 4];
            uint32_t a3 = myA[(rb + g + 8) * WSTRIDE + kt * 8 + t + 4];
#pragma unroll
            for (int nt = 0; nt < 8; nt++)
                mma_tf32(c[tt][nt], a0, a1, a2, a3, B0[nt], B1[nt]);
        }
    }

    __syncwarp();
#pragma unroll
    for (int tt = 0; tt < 2; tt++)
#pragma unroll
        for (int nt = 0; nt < 8; nt++) {
            myA[(tt * 16 + g) * CSTRIDE + nt * 4 + t]     = f2_to_bf(c[tt][nt][0], c[tt][nt][1]);
            myA[(tt * 16 + g + 8) * CSTRIDE + nt * 4 + t] = f2_to_bf(c[tt][nt][2], c[tt][nt][3]);
        }
    __syncwarp();
#pragma unroll
    for (int r = 0; r < 32; r++)
        g_xt_h[(long)(row0 + r) * 32 + lane] = myA[r * CSTRIDE + lane];
}

// ---------------- k_edge: m_e = binv * sum_{v in e} xt_v (round-10 proven, MLP-4) ----------------
__global__ void __launch_bounds__(256) k_edge() {
    int lane = threadIdx.x & 31;
    int e = blockIdx.x * 8 + (threadIdx.x >> 5);   // grid exact: N_HEDGES/8

    int beg = g_colptr[e], end = g_colptr[e + 1];
    float2 acc = make_float2(0.f, 0.f);
    for (int chunk = beg; chunk < end; chunk += 32) {
        int n = min(32, end - chunk);
        int idx = (lane < n) ? g_csrE[chunk + lane] : 0;
        int k = 0;
        for (; k + 4 <= n; k += 4) {
            int v0 = __shfl_sync(FULLM, idx, k);
            int v1 = __shfl_sync(FULLM, idx, k + 1);
            int v2 = __shfl_sync(FULLM, idx, k + 2);
            int v3 = __shfl_sync(FULLM, idx, k + 3);
            uint32_t p0 = g_xt_h[(long)v0 * 32 + lane];
            uint32_t p1 = g_xt_h[(long)v1 * 32 + lane];
            uint32_t p2 = g_xt_h[(long)v2 * 32 + lane];
            uint32_t p3 = g_xt_h[(long)v3 * 32 + lane];
            float2 f0 = bf_to_f2(p0), f1 = bf_to_f2(p1);
            float2 f2 = bf_to_f2(p2), f3 = bf_to_f2(p3);
            acc.x += (f0.x + f1.x) + (f2.x + f3.x);
            acc.y += (f0.y + f1.y) + (f2.y + f3.y);
        }
        for (; k < n; k++) {
            int v = __shfl_sync(FULLM, idx, k);
            float2 f = bf_to_f2(g_xt_h[(long)v * 32 + lane]);
            acc.x += f.x;
            acc.y += f.y;
        }
    }
    int deg = end - beg;
    float bi = deg > 0 ? 1.f / (float)deg : 0.f;
    g_m_h[(long)e * 32 + lane] = f2_to_bf(acc.x * bi, acc.y * bi);
}

// ---------------- k_node: gather m_h (MLP-4) -> relu -> mma -> staged bf16 store ----------------
__global__ void __launch_bounds__(128) k_node(const float* __restrict__ W,
                                              const float* __restrict__ b) {
    __shared__ uint32_t Ws[CH * WSTRIDE];
    __shared__ float bs[CH];
    __shared__ uint32_t As[4][16 * WSTRIDE];
    for (int i = threadIdx.x; i < CH * CH; i += 128) {
        int k = i >> 6, n = i & 63;
        Ws[n * WSTRIDE + k] = tf32r(W[i]);
    }
    if (threadIdx.x < CH) bs[threadIdx.x] = b[threadIdx.x];
    __syncthreads();

    int lane = threadIdx.x & 31;
    int wid = threadIdx.x >> 5;
    int tile = blockIdx.x * 4 + wid;
    if (tile >= N_TILES) return;
    int row0 = tile * 16;
    uint32_t* myA = As[wid];

    for (int n = 0; n < 16; n++) {
        int v = row0 + n;
        int j = g_rowptr[v], end = g_rowptr[v + 1];
        int deg = end - j;
        float2 acc = make_float2(0.f, 0.f);
        for (; j + 4 <= end; j += 4) {
            int e0 = g_csr[j], e1 = g_csr[j + 1], e2 = g_csr[j + 2], e3 = g_csr[j + 3];
            uint32_t p0 = g_m_h[(long)e0 * 32 + lane];
            uint32_t p1 = g_m_h[(long)e1 * 32 + lane];
            uint32_t p2 = g_m_h[(long)e2 * 32 + lane];
            uint32_t p3 = g_m_h[(long)e3 * 32 + lane];
            float2 f0 = bf_to_f2(p0), f1 = bf_to_f2(p1);
            float2 f2 = bf_to_f2(p2), f3 = bf_to_f2(p3);
            acc.x += (f0.x + f1.x) + (f2.x + f3.x);
            acc.y += (f0.y + f1.y) + (f2.y + f3.y);
        }
        for (; j < end; j++) {
            int e = g_csr[j];
            float2 f = bf_to_f2(g_m_h[(long)e * 32 + lane]);
            acc.x += f.x;
            acc.y += f.y;
        }
        float di = deg > 0 ? 1.f / (float)deg : 0.f;
        uint32_t h0 = tf32r(fmaxf(acc.x * di, 0.f));
        uint32_t h1 = tf32r(fmaxf(acc.y * di, 0.f));
        *(uint2*)&myA[n * WSTRIDE + 2 * lane] = make_uint2(h0, h1);
    }
    __syncwarp();

    int g = lane >> 2, t = lane & 3;
    float c[8][4];
#pragma unroll
    for (int nt = 0; nt < 8; nt++) {
        float b0 = bs[nt * 8 + t * 2], b1 = bs[nt * 8 + t * 2 + 1];
        c[nt][0] = b0; c[nt][1] = b1; c[nt][2] = b0; c[nt][3] = b1;
    }
#pragma unroll
    for (int kt = 0; kt < 8; kt++) {
        uint32_t a0 = myA[g * WSTRIDE + kt * 8 + t];
        uint32_t a1 = myA[(g + 8) * WSTRIDE + kt * 8 + t];
        uint32_t a2 = myA[g * WSTRIDE + kt * 8 + t + 4];
        uint32_t a3 = myA[(g + 8) * WSTRIDE + kt * 8 + t + 4];
#pragma unroll
        for (int nt = 0; nt < 8; nt++) {
            uint32_t b0 = Ws[(nt * 8 + g) * WSTRIDE + kt * 8 + t];
            uint32_t b1 = Ws[(nt * 8 + g) * WSTRIDE + kt * 8 + t + 4];
            mma_tf32(c[nt], a0, a1, a2, a3, b0, b1);
        }
    }

    __syncwarp();
#pragma unroll
    for (int nt = 0; nt < 8; nt++) {
        myA[g * CSTRIDE + nt * 4 + t]       = f2_to_bf(c[nt][0], c[nt][1]);
        myA[(g + 8) * CSTRIDE + nt * 4 + t] = f2_to_bf(c[nt][2], c[nt][3]);
    }
    __syncwarp();
#pragma unroll
    for (int r = 0; r < 16; r++)
        g_xt_h[(long)(row0 + r) * 32 + lane] = myA[r * CSTRIDE + lane];
}

// ---------------- conv2 pass B + pooling + fc dot (round-10 proven, MLP-2) ----------------
__global__ void __launch_bounds__(256) k_conv_c(const int* __restrict__ batch,
                                                const float* __restrict__ Wfc) {
    int lane = threadIdx.x & 31;
    int warp = blockIdx.x * 8 + (threadIdx.x >> 5);
    int base = warp * 4;
    int grp = lane >> 4, c4 = (lane & 15) * 4;
    float4 wf = *(const float4*)(Wfc + c4);

    float acc = 0.f;
    int curg = -1;
#pragma unroll
    for (int n = 0; n < 4; n++) {
        int v = base + n;
        int beg = g_rowptr[v], deg = g_rowptr[v + 1] - beg;
        float4 s = make_float4(0.f, 0.f, 0.f, 0.f);
        int j = grp;
        for (; j + 2 < deg; j += 4) {
            int e0 = g_csr[beg + j];
            int e1 = g_csr[beg + j + 2];
            uint2 p0 = *(const uint2*)(g_m_h + (long)e0 * 32 + (c4 >> 1));
            uint2 p1 = *(const uint2*)(g_m_h + (long)e1 * 32 + (c4 >> 1));
            float2 l0 = bf_to_f2(p0.x), h0 = bf_to_f2(p0.y);
            float2 l1 = bf_to_f2(p1.x), h1 = bf_to_f2(p1.y);
            s.x += l0.x + l1.x; s.y += l0.y + l1.y;
            s.z += h0.x + h1.x; s.w += h0.y + h1.y;
        }
        if (j < deg) {
            int e = g_csr[beg + j];
            uint2 pw = *(const uint2*)(g_m_h + (long)e * 32 + (c4 >> 1));
            float2 lo = bf_to_f2(pw.x), hi = bf_to_f2(pw.y);
            s.x += lo.x; s.y += lo.y; s.z += hi.x; s.w += hi.y;
        }
        s.x += __shfl_xor_sync(FULLM, s.x, 16);
        s.y += __shfl_xor_sync(FULLM, s.y, 16);
        s.z += __shfl_xor_sync(FULLM, s.z, 16);
        s.w += __shfl_xor_sync(FULLM, s.w, 16);
        float di = deg > 0 ? 1.f / (float)deg : 0.f;
        float p = 0.f;
        if (grp == 0) {
            p = fmaxf(di * s.x, 0.f) * wf.x + fmaxf(di * s.y, 0.f) * wf.y +
                fmaxf(di * s.z, 0.f) * wf.z + fmaxf(di * s.w, 0.f) * wf.w;
        }
#pragma unroll
        for (int o = 16; o > 0; o >>= 1) p += __shfl_xor_sync(FULLM, p, o);
        if (lane == 0) {
            int g = batch[v];
            if (g != curg) {
                if (curg >= 0) atomicAdd(&g_gsum[curg], acc);
                curg = g;
                acc = 0.f;
            }
            acc += p;
        }
    }
    if (lane == 0 && curg >= 0) atomicAdd(&g_gsum[curg], acc);
}

// ---------------- finalize ----------------
__global__ void k_fin(float* __restrict__ out, const float* __restrict__ bfc) {
    int g = blockIdx.x * blockDim.x + threadIdx.x;
    if (g < N_GRAPHS) {
        float cnt = fmaxf((float)g_gcnt[g], 1.f);
        out[g] = g_gsum[g] / cnt + bfc[0];
    }
}

// ---------------- launch ----------------
extern "C" void kernel_launch(void* const* d_in, const int* in_sizes, int n_in,
                              void* d_out, int out_size) {
    const float* x     = (const float*)d_in[0];
    const int*   eidx  = (const int*)d_in[1];
    const int*   row   = eidx;
    const int*   col   = eidx + N_INC;
    const int*   batch = (const int*)d_in[2];
    const float* W1    = (const float*)d_in[3];
    const float* b1    = (const float*)d_in[4];
    const float* W2    = (const float*)d_in[5];
    const float* b2    = (const float*)d_in[6];
    const float* Wfc   = (const float*)d_in[7];
    const float* bfc   = (const float*)d_in[8];
    float*       out   = (float*)d_out;

    const int XT_SMEM  = (CH * WSTRIDE + 4 * 32 * WSTRIDE) * 4;   // 52224 B
    static bool attr_done = false;
    if (!attr_done) {
        cudaFuncSetAttribute(k_xt, cudaFuncAttributeMaxDynamicSharedMemorySize, XT_SMEM);
        attr_done = true;
    }

    const int NB_HALF  = (HALF_INC + 255) / 256;       // 3907
    const int NB_XT    = (N_TILES / 2 + 3) / 4;        // 3907
    const int NB_MM    = (N_TILES + 3) / 4;            // 7813
    const int NB_EDGE  = N_HEDGES / 8;                 // 12500
    const int NB_CONVC = (N_NODES / 4) / 8;            // 15625

    k_zero1<<<512, 256>>>();
    k_zero2<<<16, 256>>>();
    k_xt<<<NB_XT, 128, XT_SMEM>>>(x, W1, b1);
    k_hist<<<NB_HALF, 256>>>(row, col, batch);   // position 4 -> gets the ncu capture
    k_scan<<<NB_SCANT, 1024>>>();
    k_fill<<<NB_HALF, 256>>>(row, col);
    k_edge<<<NB_EDGE, 256>>>();
    k_node<<<NB_MM, 128>>>(W2, b2);
    k_edge<<<NB_EDGE, 256>>>();
    k_conv_c<<<NB_CONVC, 256>>>(batch, Wfc);
    k_fin<<<2, 256>>>(out, bfc);
}

// round 14
// speedup vs baseline: 1.1265x; 1.0290x over previous
#include <cuda_runtime.h>
#include <cuda_bf16.h>
#include <cstdint>

#define N_NODES     500000
#define N_INC       2000000
#define N_HEDGES    100000
#define N_GRAPHS    512
#define CH          64
#define FULLM       0xffffffffu
#define N_TILES     31250          // N_NODES / 16 (even)
#define WSTRIDE     68             // padded smem row stride for A/W tiles
#define CSTRIDE     36             // C-stage stride: bank=(4r+c)%32 conflict-free
#define NB_SCANN    489            // ceil(N_NODES/1024)
#define NB_SCANE    98             // ceil(N_HEDGES/1024)
#define NB_SCANT    (NB_SCANN + NB_SCANE)   // 587

// ---------------- scratch (device globals; no allocation allowed) ----------------
__device__ __align__(256) uint32_t g_xt_h[(long)N_NODES * 32];   // 64 MB bf16 rows (128B each)
__device__ __align__(256) uint32_t g_m_h [(long)N_HEDGES * 32];  // 12.8 MB bf16 rows
__device__ int   g_degN[N_NODES];
__device__ int   g_degE[N_HEDGES];
__device__ int   g_rowptr[N_NODES + 1];     // node -> edges (classic CSR)
__device__ int   g_colptr[N_HEDGES + 1];    // edge -> nodes
__device__ int   g_cursor[N_NODES];
__device__ int   g_cursorE[N_HEDGES];
__device__ int   g_csr[N_INC];              // edge ids, grouped by node
__device__ int   g_csrE[N_INC];             // node ids, grouped by edge
__device__ int   g_agg [NB_SCANT];          // decoupled-lookback aggregates
__device__ int   g_pref[NB_SCANT];          // inclusive prefixes
__device__ int   g_stat[NB_SCANT];          // 0 invalid / 1 agg / 2 prefix
__device__ float g_gsum[N_GRAPHS];
__device__ int   g_gcnt[N_GRAPHS];

// ---------------- small helpers ----------------
__device__ __forceinline__ uint32_t f2_to_bf(float a, float b) {
    uint32_t r;
    asm("cvt.rn.bf16x2.f32 %0, %1, %2;" : "=r"(r) : "f"(b), "f"(a));
    return r;
}
__device__ __forceinline__ float2 bf_to_f2(uint32_t p) {
    return __bfloat1622float2(*reinterpret_cast<const __nv_bfloat162*>(&p));
}
__device__ __forceinline__ uint32_t tf32r(float f) {
    uint32_t r;
    asm("cvt.rna.tf32.f32 %0, %1;" : "=r"(r) : "f"(f));
    return r;
}
__device__ __forceinline__ void mma_tf32(float c[4],
                                         uint32_t a0, uint32_t a1, uint32_t a2, uint32_t a3,
                                         uint32_t b0, uint32_t b1) {
    asm volatile("mma.sync.aligned.m16n8k8.row.col.f32.tf32.tf32.f32 "
                 "{%0,%1,%2,%3}, {%4,%5,%6,%7}, {%8,%9}, {%0,%1,%2,%3};"
                 : "+f"(c[0]), "+f"(c[1]), "+f"(c[2]), "+f"(c[3])
                 : "r"(a0), "r"(a1), "r"(a2), "r"(a3), "r"(b0), "r"(b1));
}

// ---------------- zero scratch ----------------
__global__ void k_zero() {
    int t = blockIdx.x * blockDim.x + threadIdx.x;
    int S = gridDim.x * blockDim.x;
    for (int j = t; j < N_NODES; j += S) { g_degN[j] = 0; g_cursor[j] = 0; }
    for (int j = t; j < N_HEDGES; j += S) { g_degE[j] = 0; g_cursorE[j] = 0; }
    for (int j = t; j < N_GRAPHS; j += S) { g_gsum[j] = 0.f; g_gcnt[j] = 0; }
    for (int j = t; j < NB_SCANT; j += S) g_stat[j] = 0;
}

// ---------------- degree histograms + graph-size histogram (round-10 form) ----------------
__global__ void k_hist(const int* __restrict__ row, const int* __restrict__ col,
                       const int* __restrict__ batch) {
    int i = blockIdx.x * blockDim.x + threadIdx.x;
    if (i < N_INC) {
        atomicAdd(&g_degN[row[i]], 1);
        atomicAdd(&g_degE[col[i]], 1);
    }
    unsigned act = __ballot_sync(FULLM, i < N_NODES);
    if (i < N_NODES) {
        int g = batch[i];
        unsigned mask = __match_any_sync(act, g);
        int leader = __ffs(mask) - 1;
        if ((threadIdx.x & 31) == leader) atomicAdd(&g_gcnt[g], __popc(mask));
    }
}

// ---------------- single-kernel exclusive scans, warp-parallel decoupled lookback ----------------
// (measured 21.7 us). Classic CSR output: out[i] = exclusive prefix, out[n] = N_INC.
__global__ void k_scan() {
    int mode = blockIdx.x >= NB_SCANN;
    int blk = mode ? blockIdx.x - NB_SCANN : blockIdx.x;
    const int* __restrict__ in = mode ? g_degE : g_degN;
    int* __restrict__ out = mode ? g_colptr : g_rowptr;
    int n = mode ? N_HEDGES : N_NODES;
    int gix = blockIdx.x;

    __shared__ int sh[1024];
    __shared__ int s_off;
    int tid = threadIdx.x;
    int i = blk * 1024 + tid;
    int v = (i < n) ? in[i] : 0;
    sh[tid] = v;
    __syncthreads();
#pragma unroll
    for (int off = 1; off < 1024; off <<= 1) {
        int t = (tid >= off) ? sh[tid - off] : 0;
        __syncthreads();
        sh[tid] += t;
        __syncthreads();
    }

    if (tid >= 992) {                 // warp 31
        int lane = tid - 992;
        int total = sh[1023];
        if (blk == 0) {
            if (lane == 0) {
                g_pref[gix] = total;
                __threadfence();
                g_stat[gix] = 2;
                s_off = 0;
            }
        } else {
            if (lane == 0) {
                g_agg[gix] = total;
                __threadfence();
                g_stat[gix] = 1;
            }
            __syncwarp();
            int chainStart = gix - blk;
            int sum = 0;
            int base = gix - 1;
            while (true) {
                int p = base - lane;
                int st, val;
                if (p < chainStart) {
                    st = 2; val = 0;
                } else {
                    do { st = ((volatile int*)g_stat)[p]; } while (st == 0);
                    __threadfence();
                    val = (st == 2) ? ((volatile int*)g_pref)[p]
                                    : ((volatile int*)g_agg)[p];
                }
                unsigned pm = __ballot_sync(FULLM, st == 2);
                int firstp = __ffs(pm) - 1;
                int contrib = pm ? ((lane <= firstp) ? val : 0) : val;
#pragma unroll
                for (int o2 = 16; o2; o2 >>= 1)
                    contrib += __shfl_xor_sync(FULLM, contrib, o2);
                sum += contrib;
                if (pm) break;
                base -= 32;
            }
            if (lane == 0) {
                g_pref[gix] = sum + total;
                __threadfence();
                g_stat[gix] = 2;
                s_off = sum;
            }
        }
    }
    __syncthreads();
    if (i < n) out[i] = s_off + sh[tid] - v;   // exclusive prefix
    if (i == 0) out[n] = N_INC;                // terminator (blk 0 of each chain)
}

// ---------------- fill both CSRs (round-10 cursor form) ----------------
__global__ void k_fill(const int* __restrict__ row, const int* __restrict__ col) {
    int i = blockIdx.x * blockDim.x + threadIdx.x;
    if (i < N_INC) {
        int r = row[i], c = col[i];
        int pr = g_rowptr[r] + atomicAdd(&g_cursor[r], 1);
        g_csr[pr] = c;
        int pc = g_colptr[c] + atomicAdd(&g_cursorE[c], 1);
        g_csrE[pc] = r;
    }
}

// ---------------- k_xt: xt = x W1 + b1 via tf32 mma (proven) ----------------
extern __shared__ uint32_t dyn_smem[];
__global__ void __launch_bounds__(128) k_xt(const float* __restrict__ x,
                                            const float* __restrict__ W,
                                            const float* __restrict__ b) {
    uint32_t* Ws = dyn_smem;                      // tf32 bits, [n][k] stride 68
    __shared__ float bs[CH];
    for (int i = threadIdx.x; i < CH * CH; i += 128) {
        int k = i >> 6, n = i & 63;
        Ws[n * WSTRIDE + k] = tf32r(W[i]);
    }
    if (threadIdx.x < CH) bs[threadIdx.x] = b[threadIdx.x];
    __syncthreads();

    int lane = threadIdx.x & 31;
    int wid = threadIdx.x >> 5;
    int wg = blockIdx.x * 4 + wid;
    int tileBase = wg * 2;
    if (tileBase >= N_TILES) return;
    int row0 = tileBase * 16;
    uint32_t* myA = dyn_smem + CH * WSTRIDE + wid * (32 * WSTRIDE);

    const float* xbase = x + (long)row0 * CH;
#pragma unroll
    for (int i = 0; i < 16; i++) {
        int idx = i * 32 + lane;
        int r = idx >> 4, c4 = (idx & 15) * 4;
        float4 v = *(const float4*)(xbase + r * CH + c4);
        *(uint4*)&myA[r * WSTRIDE + c4] =
            make_uint4(tf32r(v.x), tf32r(v.y), tf32r(v.z), tf32r(v.w));
    }
    __syncwarp();

    int g = lane >> 2, t = lane & 3;
    float c[2][8][4];
#pragma unroll
    for (int tt = 0; tt < 2; tt++)
#pragma unroll
        for (int nt = 0; nt < 8; nt++) {
            float b0 = bs[nt * 8 + t * 2], b1 = bs[nt * 8 + t * 2 + 1];
            c[tt][nt][0] = b0; c[tt][nt][1] = b1; c[tt][nt][2] = b0; c[tt][nt][3] = b1;
        }

#pragma unroll
    for (int kt = 0; kt < 8; kt++) {
        uint32_t B0[8], B1[8];
#pragma unroll
        for (int nt = 0; nt < 8; nt++) {
            B0[nt] = Ws[(nt * 8 + g) * WSTRIDE + kt * 8 + t];
            B1[nt] = Ws[(nt * 8 + g) * WSTRIDE + kt * 8 + t + 4];
        }
#pragma unroll
        for (int tt = 0; tt < 2; tt++) {
            int rb = tt * 16;
            uint32_t a0 = myA[(rb + g) * WSTRIDE + kt * 8 + t];
            uint32_t a1 = myA[(rb + g + 8) * WSTRIDE + kt * 8 + t];
            uint32_t a2 = myA[(rb + g) * WSTRIDE + kt * 8 + t + 4];
            uint32_t a3 = myA[(rb + g + 8) * WSTRIDE + kt * 8 + t + 4];
#pragma unroll
            for (int nt = 0; nt < 8; nt++)
                mma_tf32(c[tt][nt], a0, a1, a2, a3, B0[nt], B1[nt]);
        }
    }

    __syncwarp();
#pragma unroll
    for (int tt = 0; tt < 2; tt++)
#pragma unroll
        for (int nt = 0; nt < 8; nt++) {
            myA[(tt * 16 + g) * CSTRIDE + nt * 4 + t]     = f2_to_bf(c[tt][nt][0], c[tt][nt][1]);
            myA[(tt * 16 + g + 8) * CSTRIDE + nt * 4 + t] = f2_to_bf(c[tt][nt][2], c[tt][nt][3]);
        }
    __syncwarp();
#pragma unroll
    for (int r = 0; r < 32; r++)
        g_xt_h[(long)(row0 + r) * 32 + lane] = myA[r * CSTRIDE + lane];
}

// ---------------- k_edge: m_e = binv * sum_{v in e} xt_v (proven, MLP-4) ----------------
__global__ void __launch_bounds__(256) k_edge() {
    int lane = threadIdx.x & 31;
    int e = blockIdx.x * 8 + (threadIdx.x >> 5);   // grid exact: N_HEDGES/8

    int beg = g_colptr[e], end = g_colptr[e + 1];
    float2 acc = make_float2(0.f, 0.f);
    for (int chunk = beg; chunk < end; chunk += 32) {
        int n = min(32, end - chunk);
        int idx = (lane < n) ? g_csrE[chunk + lane] : 0;
        int k = 0;
        for (; k + 4 <= n; k += 4) {
            int v0 = __shfl_sync(FULLM, idx, k);
            int v1 = __shfl_sync(FULLM, idx, k + 1);
            int v2 = __shfl_sync(FULLM, idx, k + 2);
            int v3 = __shfl_sync(FULLM, idx, k + 3);
            uint32_t p0 = g_xt_h[(long)v0 * 32 + lane];
            uint32_t p1 = g_xt_h[(long)v1 * 32 + lane];
            uint32_t p2 = g_xt_h[(long)v2 * 32 + lane];
            uint32_t p3 = g_xt_h[(long)v3 * 32 + lane];
            float2 f0 = bf_to_f2(p0), f1 = bf_to_f2(p1);
            float2 f2 = bf_to_f2(p2), f3 = bf_to_f2(p3);
            acc.x += (f0.x + f1.x) + (f2.x + f3.x);
            acc.y += (f0.y + f1.y) + (f2.y + f3.y);
        }
        for (; k < n; k++) {
            int v = __shfl_sync(FULLM, idx, k);
            float2 f = bf_to_f2(g_xt_h[(long)v * 32 + lane]);
            acc.x += f.x;
            acc.y += f.y;
        }
    }
    int deg = end - beg;
    float bi = deg > 0 ? 1.f / (float)deg : 0.f;
    g_m_h[(long)e * 32 + lane] = f2_to_bf(acc.x * bi, acc.y * bi);
}

// ---------------- k_node: 256 threads / 8 warps, dynamic smem (32 warps/SM vs 24) ----------------
__global__ void __launch_bounds__(256) k_node(const float* __restrict__ W,
                                              const float* __restrict__ b) {
    uint32_t* Ws = dyn_smem;                      // tf32 bits, [n][k] stride 68
    __shared__ float bs[CH];
    for (int i = threadIdx.x; i < CH * CH; i += 256) {
        int k = i >> 6, n = i & 63;
        Ws[n * WSTRIDE + k] = tf32r(W[i]);
    }
    if (threadIdx.x < CH) bs[threadIdx.x] = b[threadIdx.x];
    __syncthreads();

    int lane = threadIdx.x & 31;
    int wid = threadIdx.x >> 5;
    int tile = blockIdx.x * 8 + wid;
    if (tile >= N_TILES) return;
    int row0 = tile * 16;
    uint32_t* myA = dyn_smem + CH * WSTRIDE + wid * (16 * WSTRIDE);

    for (int n = 0; n < 16; n++) {
        int v = row0 + n;
        int j = g_rowptr[v], end = g_rowptr[v + 1];
        int deg = end - j;
        float2 acc = make_float2(0.f, 0.f);
        for (; j + 4 <= end; j += 4) {
            int e0 = g_csr[j], e1 = g_csr[j + 1], e2 = g_csr[j + 2], e3 = g_csr[j + 3];
            uint32_t p0 = g_m_h[(long)e0 * 32 + lane];
            uint32_t p1 = g_m_h[(long)e1 * 32 + lane];
            uint32_t p2 = g_m_h[(long)e2 * 32 + lane];
            uint32_t p3 = g_m_h[(long)e3 * 32 + lane];
            float2 f0 = bf_to_f2(p0), f1 = bf_to_f2(p1);
            float2 f2 = bf_to_f2(p2), f3 = bf_to_f2(p3);
            acc.x += (f0.x + f1.x) + (f2.x + f3.x);
            acc.y += (f0.y + f1.y) + (f2.y + f3.y);
        }
        for (; j < end; j++) {
            int e = g_csr[j];
            float2 f = bf_to_f2(g_m_h[(long)e * 32 + lane]);
            acc.x += f.x;
            acc.y += f.y;
        }
        float di = deg > 0 ? 1.f / (float)deg : 0.f;
        uint32_t h0 = tf32r(fmaxf(acc.x * di, 0.f));
        uint32_t h1 = tf32r(fmaxf(acc.y * di, 0.f));
        *(uint2*)&myA[n * WSTRIDE + 2 * lane] = make_uint2(h0, h1);
    }
    __syncwarp();

    int g = lane >> 2, t = lane & 3;
    float c[8][4];
#pragma unroll
    for (int nt = 0; nt < 8; nt++) {
        float b0 = bs[nt * 8 + t * 2], b1 = bs[nt * 8 + t * 2 + 1];
        c[nt][0] = b0; c[nt][1] = b1; c[nt][2] = b0; c[nt][3] = b1;
    }
#pragma unroll
    for (int kt = 0; kt < 8; kt++) {
        uint32_t a0 = myA[g * WSTRIDE + kt * 8 + t];
        uint32_t a1 = myA[(g + 8) * WSTRIDE + kt * 8 + t];
        uint32_t a2 = myA[g * WSTRIDE + kt * 8 + t + 4];
        uint32_t a3 = myA[(g + 8) * WSTRIDE + kt * 8 + t + 4];
#pragma unroll
        for (int nt = 0; nt < 8; nt++) {
            uint32_t b0 = Ws[(nt * 8 + g) * WSTRIDE + kt * 8 + t];
            uint32_t b1 = Ws[(nt * 8 + g) * WSTRIDE + kt * 8 + t + 4];
            mma_tf32(c[nt], a0, a1, a2, a3, b0, b1);
        }
    }

    __syncwarp();
#pragma unroll
    for (int nt = 0; nt < 8; nt++) {
        myA[g * CSTRIDE + nt * 4 + t]       = f2_to_bf(c[nt][0], c[nt][1]);
        myA[(g + 8) * CSTRIDE + nt * 4 + t] = f2_to_bf(c[nt][2], c[nt][3]);
    }
    __syncwarp();
#pragma unroll
    for (int r = 0; r < 16; r++)
        g_xt_h[(long)(row0 + r) * 32 + lane] = myA[r * CSTRIDE + lane];
}

// ---------------- conv2 pass B + pooling + fc dot (proven, MLP-2) ----------------
__global__ void __launch_bounds__(256) k_conv_c(const int* __restrict__ batch,
                                                const float* __restrict__ Wfc) {
    int lane = threadIdx.x & 31;
    int warp = blockIdx.x * 8 + (threadIdx.x >> 5);
    int base = warp * 4;
    int grp = lane >> 4, c4 = (lane & 15) * 4;
    float4 wf = *(const float4*)(Wfc + c4);

    float acc = 0.f;
    int curg = -1;
#pragma unroll
    for (int n = 0; n < 4; n++) {
        int v = base + n;
        int beg = g_rowptr[v], deg = g_rowptr[v + 1] - beg;
        float4 s = make_float4(0.f, 0.f, 0.f, 0.f);
        int j = grp;
        for (; j + 2 < deg; j += 4) {
            int e0 = g_csr[beg + j];
            int e1 = g_csr[beg + j + 2];
            uint2 p0 = *(const uint2*)(g_m_h + (long)e0 * 32 + (c4 >> 1));
            uint2 p1 = *(const uint2*)(g_m_h + (long)e1 * 32 + (c4 >> 1));
            float2 l0 = bf_to_f2(p0.x), h0 = bf_to_f2(p0.y);
            float2 l1 = bf_to_f2(p1.x), h1 = bf_to_f2(p1.y);
            s.x += l0.x + l1.x; s.y += l0.y + l1.y;
            s.z += h0.x + h1.x; s.w += h0.y + h1.y;
        }
        if (j < deg) {
            int e = g_csr[beg + j];
            uint2 pw = *(const uint2*)(g_m_h + (long)e * 32 + (c4 >> 1));
            float2 lo = bf_to_f2(pw.x), hi = bf_to_f2(pw.y);
            s.x += lo.x; s.y += lo.y; s.z += hi.x; s.w += hi.y;
        }
        s.x += __shfl_xor_sync(FULLM, s.x, 16);
        s.y += __shfl_xor_sync(FULLM, s.y, 16);
        s.z += __shfl_xor_sync(FULLM, s.z, 16);
        s.w += __shfl_xor_sync(FULLM, s.w, 16);
        float di = deg > 0 ? 1.f / (float)deg : 0.f;
        float p = 0.f;
        if (grp == 0) {
            p = fmaxf(di * s.x, 0.f) * wf.x + fmaxf(di * s.y, 0.f) * wf.y +
                fmaxf(di * s.z, 0.f) * wf.z + fmaxf(di * s.w, 0.f) * wf.w;
        }
#pragma unroll
        for (int o = 16; o > 0; o >>= 1) p += __shfl_xor_sync(FULLM, p, o);
        if (lane == 0) {
            int g = batch[v];
            if (g != curg) {
                if (curg >= 0) atomicAdd(&g_gsum[curg], acc);
                curg = g;
                acc = 0.f;
            }
            acc += p;
        }
    }
    if (lane == 0 && curg >= 0) atomicAdd(&g_gsum[curg], acc);
}

// ---------------- finalize ----------------
__global__ void k_fin(float* __restrict__ out, const float* __restrict__ bfc) {
    int g = blockIdx.x * blockDim.x + threadIdx.x;
    if (g < N_GRAPHS) {
        float cnt = fmaxf((float)g_gcnt[g], 1.f);
        out[g] = g_gsum[g] / cnt + bfc[0];
    }
}

// ---------------- launch ----------------
extern "C" void kernel_launch(void* const* d_in, const int* in_sizes, int n_in,
                              void* d_out, int out_size) {
    const float* x     = (const float*)d_in[0];
    const int*   eidx  = (const int*)d_in[1];
    const int*   row   = eidx;
    const int*   col   = eidx + N_INC;
    const int*   batch = (const int*)d_in[2];
    const float* W1    = (const float*)d_in[3];
    const float* b1    = (const float*)d_in[4];
    const float* W2    = (const float*)d_in[5];
    const float* b2    = (const float*)d_in[6];
    const float* Wfc   = (const float*)d_in[7];
    const float* bfc   = (const float*)d_in[8];
    float*       out   = (float*)d_out;

    const int XT_SMEM  = (CH * WSTRIDE + 4 * 32 * WSTRIDE) * 4;   // 52224 B
    const int ND_SMEM  = (CH * WSTRIDE + 8 * 16 * WSTRIDE) * 4;   // 52224 B
    static bool attr_done = false;
    if (!attr_done) {
        cudaFuncSetAttribute(k_xt, cudaFuncAttributeMaxDynamicSharedMemorySize, XT_SMEM);
        cudaFuncSetAttribute(k_node, cudaFuncAttributeMaxDynamicSharedMemorySize, ND_SMEM);
        attr_done = true;
    }

    const int NB_INC   = (N_INC + 255) / 256;          // 7813
    const int NB_XT    = (N_TILES / 2 + 3) / 4;        // 3907
    const int NB_ND    = (N_TILES + 7) / 8;            // 3907
    const int NB_EDGE  = N_HEDGES / 8;                 // 12500
    const int NB_CONVC = (N_NODES / 4) / 8;            // 15625

    k_zero<<<512, 256>>>();
    k_hist<<<NB_INC, 256>>>(row, col, batch);
    k_scan<<<NB_SCANT, 1024>>>();
    k_fill<<<NB_INC, 256>>>(row, col);     // position 4 -> gets the ncu capture
    k_xt<<<NB_XT, 128, XT_SMEM>>>(x, W1, b1);
    k_edge<<<NB_EDGE, 256>>>();
    k_node<<<NB_ND, 256, ND_SMEM>>>(W2, b2);
    k_edge<<<NB_EDGE, 256>>>();
    k_conv_c<<<NB_CONVC, 256>>>(batch, Wfc);
    k_fin<<<2, 256>>>(out, bfc);
}